// round 14
// baseline (speedup 1.0000x reference)
#include <cuda_runtime.h>
#include <cuda_fp16.h>
#include <math.h>
#include <stdint.h>

// ---------------- problem constants ----------------
#define Bv     64
#define Lv     256
#define Ev     1600
#define Pv     100
#define Nv     400          // P*4 (no padding anywhere)
#define NTILE  80           // per-CTA n tile (5 * 80 = 400 exact)
#define Mv     16384        // B*L
#define Kv     1600
#define NCH    25           // Kv/64

// output layout (floats)
#define OFF_D0   6400
#define OFF_D1   556928
#define OFF_D2   1084928
#define OFF_FC   1606592

// ---------------- device scratch ----------------
static __device__ float g_Yt[(size_t)Nv * Mv];   // Y^T [n][m]
static __device__ float g_S[Mv];                 // row sum of squares
static __device__ float g_P2[Pv];                // proto sum of squares
// fp16 chunked B: row = 64 k values = 128 B
static __device__ __align__(16) unsigned char g_Bc[(size_t)NCH * Nv * 128];   // [kc][n][128]

// ---------------- smem layout (per CTA, dynamic) ----------------
#define ROWB      144                    // padded smem row stride
#define ASZ       (128 * ROWB)           // 18432
#define BOFF      ASZ
#define BUFSTRIDE (ASZ + 80 * ROWB)      // 29952
#define SMEM_DYN  (2 * BUFSTRIDE)        // 59904

__device__ __forceinline__ uint32_t s2u(const void* p) {
    uint32_t a;
    asm("{ .reg .u64 t; cvta.to.shared.u64 t, %1; cvt.u32.u64 %0, t; }" : "=r"(a) : "l"(p));
    return a;
}

#define CP_ASYNC16(dst, src) \
    asm volatile("cp.async.cg.shared.global [%0], [%1], 16;" :: "r"(dst), "l"(src) : "memory")
#define CP_COMMIT() asm volatile("cp.async.commit_group;" ::: "memory")
#define CP_WAIT(n)  asm volatile("cp.async.wait_group %0;" :: "n"(n) : "memory")

#define LDM_X4(r0, r1, r2, r3, a) \
    asm volatile("ldmatrix.sync.aligned.m8n8.x4.shared.b16 {%0,%1,%2,%3}, [%4];" \
                 : "=r"(r0), "=r"(r1), "=r"(r2), "=r"(r3) : "r"(a))
#define LDM_X2(r0, r1, a) \
    asm volatile("ldmatrix.sync.aligned.m8n8.x2.shared.b16 {%0,%1}, [%2];" \
                 : "=r"(r0), "=r"(r1) : "r"(a))

// fp16 accumulate, fp16 inputs
#define MMAF16(d, a, b) \
    asm volatile("mma.sync.aligned.m16n8k16.row.col.f16.f16.f16.f16 " \
                 "{%0,%1}, {%2,%3,%4,%5}, {%6,%7}, {%0,%1};" \
                 : "+r"((d)[0]), "+r"((d)[1]) \
                 : "r"((a)[0]), "r"((a)[1]), "r"((a)[2]), "r"((a)[3]), \
                   "r"((b)[0]), "r"((b)[1]))

// ---------------- prep B: proto -> fp16 chunked + P2 + zero FC ----------------
__global__ void __launch_bounds__(256)
prep_b_kernel(const float* __restrict__ proto, float* __restrict__ out) {
    int p = blockIdx.x;                                     // 0..99
    if (p == 0 && threadIdx.x < 2 * Bv) out[OFF_FC + threadIdx.x] = 0.0f;
    __shared__ float red[256];
    float s = 0.0f;
    for (int i = threadIdx.x; i < Ev * 4; i += 256) {
        int e = i >> 2, t = i & 3;
        float v = proto[(size_t)p * (Ev * 4) + i];
        s += v * v;
        int n = 4 * p + t;
        int kc = e >> 6, dk = e & 63;
        *reinterpret_cast<__half*>(
            g_Bc + ((size_t)kc * Nv + n) * 128 + dk * 2) = __float2half_rn(v);
    }
    red[threadIdx.x] = s;
    __syncthreads();
    for (int st = 128; st > 0; st >>= 1) {
        if (threadIdx.x < st) red[threadIdx.x] += red[threadIdx.x + st];
        __syncthreads();
    }
    if (threadIdx.x == 0) g_P2[p] = red[0];
}

// ---------------- A load+convert helper: 32 fp32 -> 4 uint4 (fp16x8 each) --------
__device__ __forceinline__ void load_conv(const float4* __restrict__ src,
                                          uint4 w[4], float& ssq) {
    #pragma unroll
    for (int j = 0; j < 4; ++j) {
        float4 a = src[2 * j], b = src[2 * j + 1];
        ssq += a.x * a.x + a.y * a.y + a.z * a.z + a.w * a.w
             + b.x * b.x + b.y * b.y + b.z * b.z + b.w * b.w;
        __half2 p0 = __floats2half2_rn(a.x, a.y);
        __half2 p1 = __floats2half2_rn(a.z, a.w);
        __half2 p2 = __floats2half2_rn(b.x, b.y);
        __half2 p3 = __floats2half2_rn(b.z, b.w);
        w[j].x = *reinterpret_cast<uint32_t*>(&p0);
        w[j].y = *reinterpret_cast<uint32_t*>(&p1);
        w[j].z = *reinterpret_cast<uint32_t*>(&p2);
        w[j].w = *reinterpret_cast<uint32_t*>(&p3);
    }
}

__device__ __forceinline__ void sts_a(char* dst, const uint4 w[4]) {
    #pragma unroll
    for (int j = 0; j < 4; ++j)
        *reinterpret_cast<uint4*>(dst + j * 16) = w[j];
}

// ---------------- HMMA GEMM: Yt[n][m] = sum_k X[m][k]*W[k][n] ----------------
// grid (5, 128): 128x80 per CTA; A converted in-kernel from X (fp32, staged 1 ahead),
// B via cp.async from g_Bc (staged 2 ahead); chunk K=64; fused sumsq (nb==0).
__device__ __forceinline__ void issue_b(uint32_t sbuf, int kc, int n0, int tid) {
    const char* bsrc = (const char*)(g_Bc + ((size_t)kc * Nv + n0) * 128);
    #pragma unroll
    for (int u = 0; u < 2; ++u) {                     // 640 = 80 rows * 8 quads
        int i = tid + u * 256;
        CP_ASYNC16(sbuf + BOFF + (i >> 3) * ROWB + (i & 7) * 16, bsrc + i * 16);
    }
    if (tid < 128) {
        int i = tid + 512;
        CP_ASYNC16(sbuf + BOFF + (i >> 3) * ROWB + (i & 7) * 16, bsrc + i * 16);
    }
    CP_COMMIT();
}

__global__ void __launch_bounds__(256, 2)
gemm_mma_kernel(const float* __restrict__ X) {
    extern __shared__ __align__(128) char smem[];
    const uint32_t sb = s2u(smem);
    const int tid  = threadIdx.x;
    const int wid  = tid >> 5;
    const int lane = tid & 31;
    const int nb = blockIdx.x;              // 0..4
    const int m0 = blockIdx.y * 128;
    const int n0 = nb * NTILE;

    const int m_warp = (wid >> 1) * 32;     // 0,32,64,96
    const int n_warp = (wid & 1) * 40;      // 0,40

    const uint32_t aA = sb + (uint32_t)(m_warp + (lane & 15)) * ROWB + (lane >> 4) * 16;
    const uint32_t aB4 = sb + BOFF +
        (uint32_t)(n_warp + ((lane >> 4) << 3) + (lane & 7)) * ROWB + ((lane >> 3) & 1) * 16;
    const int l15 = lane & 15;
    const uint32_t aB2 = sb + BOFF +
        (uint32_t)(n_warp + 32 + (l15 & 7)) * ROWB + ((l15 >> 3) & 1) * 16;

    // A global source: this thread's 32-float strip per chunk
    const int r = tid >> 1;                 // row 0..127
    const int h = tid & 1;                  // k half (32 floats)
    const float4* xs = reinterpret_cast<const float4*>(X + (size_t)(m0 + r) * Kv) + h * 8;
    char* aDst0 = smem + r * ROWB + h * 64; // + buf*BUFSTRIDE

    float acc[2][5][4];
    uint32_t acc16[2][5][2];
    #pragma unroll
    for (int i = 0; i < 2; ++i)
        #pragma unroll
        for (int j = 0; j < 5; ++j) {
            acc16[i][j][0] = 0u; acc16[i][j][1] = 0u;
            #pragma unroll
            for (int q = 0; q < 4; ++q) acc[i][j][q] = 0.0f;
        }

    float ssq = 0.0f;
    uint4 rW[4];

    // ---- prologue: A0 -> buf0; B0 -> buf0; A1 -> regs; B1 -> buf1 ----
    load_conv(xs, rW, ssq);
    sts_a(aDst0, rW);
    issue_b(sb, 0, n0, tid);
    load_conv(xs + 16, rW, ssq);
    issue_b(sb + BUFSTRIDE, 1, n0, tid);
    CP_WAIT(1);
    __syncthreads();

    for (int kc = 0; kc < NCH; ++kc) {
        const uint32_t bo = (kc & 1) ? BUFSTRIDE : 0;
        // ---- compute chunk kc: 4 k16 steps ----
        #pragma unroll
        for (int ks = 0; ks < 4; ++ks) {
            uint32_t afr[2][4];
            #pragma unroll
            for (int mf = 0; mf < 2; ++mf)
                LDM_X4(afr[mf][0], afr[mf][1], afr[mf][2], afr[mf][3],
                       aA + bo + mf * (16 * ROWB) + ks * 32);
            uint32_t bfr[5][2];
            #pragma unroll
            for (int p = 0; p < 2; ++p)
                LDM_X4(bfr[2 * p][0], bfr[2 * p][1], bfr[2 * p + 1][0], bfr[2 * p + 1][1],
                       aB4 + bo + p * (16 * ROWB) + ks * 32);
            LDM_X2(bfr[4][0], bfr[4][1], aB2 + bo + ks * 32);
            #pragma unroll
            for (int mf = 0; mf < 2; ++mf)
                #pragma unroll
                for (int nf = 0; nf < 5; ++nf)
                    MMAF16(acc16[mf][nf], afr[mf], bfr[nf]);
        }
        // ---- promote fp16 segment -> fp32 every 2 chunks (and at the end) ----
        if ((kc & 1) || kc == NCH - 1) {
            #pragma unroll
            for (int mf = 0; mf < 2; ++mf)
                #pragma unroll
                for (int nf = 0; nf < 5; ++nf) {
                    __half2 h0 = *reinterpret_cast<__half2*>(&acc16[mf][nf][0]);
                    __half2 h1 = *reinterpret_cast<__half2*>(&acc16[mf][nf][1]);
                    float2 f0 = __half22float2(h0);
                    float2 f1 = __half22float2(h1);
                    acc[mf][nf][0] += f0.x; acc[mf][nf][1] += f0.y;
                    acc[mf][nf][2] += f1.x; acc[mf][nf][3] += f1.y;
                    acc16[mf][nf][0] = 0u;  acc16[mf][nf][1] = 0u;
                }
        }
        // ---- stage A(kc+1) from regs; prefetch A(kc+2) + B(kc+2) ----
        if (kc < NCH - 1) {
            __syncthreads();
            const uint32_t bn = (kc & 1) ? 0 : BUFSTRIDE;   // next buffer
            sts_a(aDst0 + bn, rW);
            if (kc < NCH - 2) {
                load_conv(xs + (kc + 2) * 16, rW, ssq);
                issue_b(sb + bo, kc + 2, n0, tid);
                CP_WAIT(1);
            } else {
                CP_WAIT(0);
            }
            __syncthreads();
        }
    }

    // ---- fused sumsq (nb==0 only): combine the 2 threads of each row ----
    if (nb == 0) {
        float tot = ssq + __shfl_xor_sync(0xffffffffu, ssq, 1);
        if (h == 0) g_S[m0 + r] = tot;
    }

    // ---- epilogue: acc -> g_Yt[n][m]  (N exact: no guards) ----
    #pragma unroll
    for (int mf = 0; mf < 2; ++mf) {
        const int mbase = m0 + m_warp + mf * 16 + (lane >> 2);
        #pragma unroll
        for (int nf = 0; nf < 5; ++nf) {
            const int nbase = n0 + n_warp + nf * 8 + 2 * (lane & 3);
            g_Yt[(size_t)nbase * Mv + mbase]           = acc[mf][nf][0];
            g_Yt[(size_t)(nbase + 1) * Mv + mbase]     = acc[mf][nf][1];
            g_Yt[(size_t)nbase * Mv + mbase + 8]       = acc[mf][nf][2];
            g_Yt[(size_t)(nbase + 1) * Mv + mbase + 8] = acc[mf][nf][3];
        }
    }
}

// ---------------- distances + per-(b,p) min + fused fc ----------------
__global__ void __launch_bounds__(256)
dist_kernel(float* __restrict__ out, const float* __restrict__ fcw) {
    int idx  = blockIdx.x * 8 + (threadIdx.x >> 5);   // (b,p), grid 800 -> 6400
    int lane = threadIdx.x & 31;
    int p = idx % Pv;
    int b = idx / Pv;
    int g = (p < 34) ? 0 : (p < 67) ? 1 : 2;
    int d = g + 1;
    int Lout = Lv - 3 * d;                             // 253/250/247
    int pbase = (g == 0) ? 0 : (g == 1) ? 34 : 67;
    int nf = (g == 0) ? 34 : 33;
    size_t dbase = (g == 0) ? OFF_D0 : (g == 1) ? OFF_D1 : OFF_D2;
    float* orow = out + dbase + ((size_t)b * nf + (p - pbase)) * Lout;

    const float* y0 = g_Yt + (size_t)(p * 4) * Mv + b * Lv;
    const float* s0 = g_S + b * Lv;
    const float p2 = g_P2[p];

    float mn = 3.402823466e38f;
    #pragma unroll
    for (int it = 0; it < 7; ++it) {                   // l <= 223 always in-bounds
        int l = lane + it * 32;
        float xp = 0.0f, x2 = 0.0f;
        #pragma unroll
        for (int k = 0; k < 4; ++k) {
            xp += y0[(size_t)k * Mv + l + k * d];
            x2 += s0[l + k * d];
        }
        float val = sqrtf(fabsf(x2 - 2.0f * xp + p2));
        orow[l] = val;
        mn = fminf(mn, val);
    }
    {   // tail: l = lane + 224, guard against Lout
        int l = lane + 224;
        if (l < Lout) {
            float xp = 0.0f, x2 = 0.0f;
            #pragma unroll
            for (int k = 0; k < 4; ++k) {
                xp += y0[(size_t)k * Mv + l + k * d];
                x2 += s0[l + k * d];
            }
            float val = sqrtf(fabsf(x2 - 2.0f * xp + p2));
            orow[l] = val;
            mn = fminf(mn, val);
        }
    }
    #pragma unroll
    for (int o = 16; o > 0; o >>= 1) mn = fminf(mn, __shfl_xor_sync(0xffffffffu, mn, o));
    if (lane == 0) {
        out[b * Pv + p] = mn;
        atomicAdd(out + OFF_FC + b * 2 + 0, mn * fcw[p]);
        atomicAdd(out + OFF_FC + b * 2 + 1, mn * fcw[Pv + p]);
    }
}

// ---------------- launch ----------------
extern "C" void kernel_launch(void* const* d_in, const int* in_sizes, int n_in,
                              void* d_out, int out_size) {
    const float* emb   = (const float*)d_in[0];   // [64,256,1600]
    const float* proto = (const float*)d_in[1];   // [100,1600,4]
    const float* fcw   = (const float*)d_in[2];   // [2,100]
    float* out = (float*)d_out;

    static int smem_set = 0;
    if (!smem_set) {
        cudaFuncSetAttribute(gemm_mma_kernel,
                             cudaFuncAttributeMaxDynamicSharedMemorySize, SMEM_DYN);
        smem_set = 1;
    }

    prep_b_kernel<<<100, 256>>>(proto, out);
    gemm_mma_kernel<<<dim3(5, 128), 256, SMEM_DYN>>>(emb);
    dist_kernel<<<800, 256>>>(out, fcw);
}

// round 15
// speedup vs baseline: 1.8955x; 1.8955x over previous
#include <cuda_runtime.h>
#include <cuda_fp16.h>
#include <math.h>
#include <stdint.h>

// ---------------- problem constants ----------------
#define Bv     64
#define Lv     256
#define Ev     1600
#define Pv     100
#define Nv     400          // P*4 (no padding anywhere)
#define NTILE  80           // per-CTA n tile (5 * 80 = 400 exact)
#define Mv     16384        // B*L
#define Kv     1600
#define NCH    25           // Kv/64

// output layout (floats)
#define OFF_D0   6400
#define OFF_D1   556928
#define OFF_D2   1084928
#define OFF_FC   1606592

// ---------------- device scratch ----------------
static __device__ float g_Yt[(size_t)Nv * Mv];   // Y^T [n][m]
static __device__ float g_S[Mv];                 // row sum of squares
static __device__ float g_P2[Pv];                // proto sum of squares
static __device__ int   g_Flag[320];             // per (nb, mb-pair) completion flags
// fp16 chunked operands: row = 64 k values = 128 B
static __device__ __align__(16) unsigned char g_Xc[(size_t)NCH * Mv * 128];   // [kc][m][128]
static __device__ __align__(16) unsigned char g_Bc[(size_t)NCH * Nv * 128];   // [kc][n][128]

// ---------------- smem layout (per CTA, dynamic) ----------------
#define ROWB      144                    // padded smem row stride
#define ASZ       (128 * ROWB)           // 18432
#define BOFF      ASZ
#define BUFSTRIDE (ASZ + 80 * ROWB)      // 29952
#define SMEM_DYN  (2 * BUFSTRIDE)        // 59904

__device__ __forceinline__ uint32_t s2u(const void* p) {
    uint32_t a;
    asm("{ .reg .u64 t; cvta.to.shared.u64 t, %1; cvt.u32.u64 %0, t; }" : "=r"(a) : "l"(p));
    return a;
}

#define CP_ASYNC16(dst, src) \
    asm volatile("cp.async.cg.shared.global [%0], [%1], 16;" :: "r"(dst), "l"(src) : "memory")
#define CP_COMMIT() asm volatile("cp.async.commit_group;" ::: "memory")
#define CP_WAIT(n)  asm volatile("cp.async.wait_group %0;" :: "n"(n) : "memory")

#define LDM_X4(r0, r1, r2, r3, a) \
    asm volatile("ldmatrix.sync.aligned.m8n8.x4.shared.b16 {%0,%1,%2,%3}, [%4];" \
                 : "=r"(r0), "=r"(r1), "=r"(r2), "=r"(r3) : "r"(a))
#define LDM_X2(r0, r1, a) \
    asm volatile("ldmatrix.sync.aligned.m8n8.x2.shared.b16 {%0,%1}, [%2];" \
                 : "=r"(r0), "=r"(r1) : "r"(a))

// fp16 accumulate, fp16 inputs
#define MMAF16(d, a, b) \
    asm volatile("mma.sync.aligned.m16n8k16.row.col.f16.f16.f16.f16 " \
                 "{%0,%1}, {%2,%3,%4,%5}, {%6,%7}, {%0,%1};" \
                 : "+r"((d)[0]), "+r"((d)[1]) \
                 : "r"((a)[0]), "r"((a)[1]), "r"((a)[2]), "r"((a)[3]), \
                   "r"((b)[0]), "r"((b)[1]))

// ---------------- fused prep: X->fp16 chunked + sumsq, proto->fp16 chunked + P2 -----
__global__ void __launch_bounds__(256)
prep_kernel(const float* __restrict__ X, const float* __restrict__ proto,
            float* __restrict__ out) {
    if (blockIdx.x < 2048) {
        // ---- X path: warp per row ----
        int m    = blockIdx.x * 8 + (threadIdx.x >> 5);
        int lane = threadIdx.x & 31;
        const float4* src = reinterpret_cast<const float4*>(X + (size_t)m * Ev);
        float ssq = 0.0f;
        #pragma unroll
        for (int it = 0; it < 7; ++it) {
            int j = lane + it * 32;
            if (j < 200) {
                float4 a = src[2 * j], b = src[2 * j + 1];
                ssq += a.x * a.x + a.y * a.y + a.z * a.z + a.w * a.w
                     + b.x * b.x + b.y * b.y + b.z * b.z + b.w * b.w;
                __half2 p0 = __floats2half2_rn(a.x, a.y);
                __half2 p1 = __floats2half2_rn(a.z, a.w);
                __half2 p2 = __floats2half2_rn(b.x, b.y);
                __half2 p3 = __floats2half2_rn(b.z, b.w);
                uint4 w;
                w.x = *reinterpret_cast<uint32_t*>(&p0);
                w.y = *reinterpret_cast<uint32_t*>(&p1);
                w.z = *reinterpret_cast<uint32_t*>(&p2);
                w.w = *reinterpret_cast<uint32_t*>(&p3);
                int kc = j >> 3, dk = j & 7;
                *reinterpret_cast<uint4*>(g_Xc + ((size_t)kc * Mv + m) * 128 + dk * 16) = w;
            }
        }
        #pragma unroll
        for (int o = 16; o > 0; o >>= 1) ssq += __shfl_xor_sync(0xffffffffu, ssq, o);
        if (lane == 0) g_S[m] = ssq;
    } else {
        // ---- B path: block per proto ----
        int p = blockIdx.x - 2048;                          // 0..99
        if (p == 0) {
            if (threadIdx.x < 2 * Bv) out[OFF_FC + threadIdx.x] = 0.0f;
            for (int i = threadIdx.x; i < 320; i += 256) g_Flag[i] = 0;
        }
        __shared__ float red[256];
        float s = 0.0f;
        for (int i = threadIdx.x; i < Ev * 4; i += 256) {
            int e = i >> 2, t = i & 3;
            float v = proto[(size_t)p * (Ev * 4) + i];
            s += v * v;
            int n = 4 * p + t;
            int kc = e >> 6, dk = e & 63;
            *reinterpret_cast<__half*>(
                g_Bc + ((size_t)kc * Nv + n) * 128 + dk * 2) = __float2half_rn(v);
        }
        red[threadIdx.x] = s;
        __syncthreads();
        for (int st = 128; st > 0; st >>= 1) {
            if (threadIdx.x < st) red[threadIdx.x] += red[threadIdx.x + st];
            __syncthreads();
        }
        if (threadIdx.x == 0) g_P2[p] = red[0];
    }
}

// ---------------- HMMA GEMM + fused dist/fc tail ----------------
// grid (5, 128): 128x80 per CTA; 8 warps (4M x 2N), warp tile 32x40; chunk K=64.
// fp16 accumulation over 2-chunk segments (K=128), promoted into fp32.
// The second CTA of each (nb, mb-pair) to finish computes dist for its 20 (b,p).
__device__ __forceinline__ void issue_chunk(uint32_t sbuf, int kc, int m0, int n0, int tid) {
    const char* asrc = (const char*)(g_Xc + ((size_t)kc * Mv + m0) * 128);
    #pragma unroll
    for (int u = 0; u < 4; ++u) {
        int i = tid + u * 256;                        // 1024 = 128 rows * 8 quads
        CP_ASYNC16(sbuf + (i >> 3) * ROWB + (i & 7) * 16, asrc + i * 16);
    }
    const char* bsrc = (const char*)(g_Bc + ((size_t)kc * Nv + n0) * 128);
    #pragma unroll
    for (int u = 0; u < 2; ++u) {                     // 640 = 80 rows * 8 quads
        int i = tid + u * 256;
        CP_ASYNC16(sbuf + BOFF + (i >> 3) * ROWB + (i & 7) * 16, bsrc + i * 16);
    }
    if (tid < 128) {
        int i = tid + 512;
        CP_ASYNC16(sbuf + BOFF + (i >> 3) * ROWB + (i & 7) * 16, bsrc + i * 16);
    }
    CP_COMMIT();
}

__global__ void __launch_bounds__(256, 2)
gemm_mma_kernel(float* __restrict__ out, const float* __restrict__ fcw) {
    extern __shared__ __align__(128) char smem[];
    const uint32_t sb = s2u(smem);
    const int tid  = threadIdx.x;
    const int wid  = tid >> 5;
    const int lane = tid & 31;
    const int nb = blockIdx.x;              // 0..4
    const int m0 = blockIdx.y * 128;
    const int n0 = nb * NTILE;

    const int m_warp = (wid >> 1) * 32;     // 0,32,64,96
    const int n_warp = (wid & 1) * 40;      // 0,40

    const uint32_t aA = sb + (uint32_t)(m_warp + (lane & 15)) * ROWB + (lane >> 4) * 16;
    const uint32_t aB4 = sb + BOFF +
        (uint32_t)(n_warp + ((lane >> 4) << 3) + (lane & 7)) * ROWB + ((lane >> 3) & 1) * 16;
    const int l15 = lane & 15;
    const uint32_t aB2 = sb + BOFF +
        (uint32_t)(n_warp + 32 + (l15 & 7)) * ROWB + ((l15 >> 3) & 1) * 16;

    float acc[2][5][4];
    uint32_t acc16[2][5][2];
    #pragma unroll
    for (int i = 0; i < 2; ++i)
        #pragma unroll
        for (int j = 0; j < 5; ++j) {
            acc16[i][j][0] = 0u; acc16[i][j][1] = 0u;
            #pragma unroll
            for (int q = 0; q < 4; ++q) acc[i][j][q] = 0.0f;
        }

    // prologue: chunks 0,1 in flight
    issue_chunk(sb, 0, m0, n0, tid);
    issue_chunk(sb + BUFSTRIDE, 1, m0, n0, tid);
    CP_WAIT(1);
    __syncthreads();

    for (int kc = 0; kc < NCH; ++kc) {
        const uint32_t bo = (kc & 1) ? BUFSTRIDE : 0;
        // ---- compute chunk kc: 4 k16 steps ----
        #pragma unroll
        for (int ks = 0; ks < 4; ++ks) {
            uint32_t afr[2][4];
            #pragma unroll
            for (int mf = 0; mf < 2; ++mf)
                LDM_X4(afr[mf][0], afr[mf][1], afr[mf][2], afr[mf][3],
                       aA + bo + mf * (16 * ROWB) + ks * 32);
            uint32_t bfr[5][2];
            #pragma unroll
            for (int p = 0; p < 2; ++p)
                LDM_X4(bfr[2 * p][0], bfr[2 * p][1], bfr[2 * p + 1][0], bfr[2 * p + 1][1],
                       aB4 + bo + p * (16 * ROWB) + ks * 32);
            LDM_X2(bfr[4][0], bfr[4][1], aB2 + bo + ks * 32);
            #pragma unroll
            for (int mf = 0; mf < 2; ++mf)
                #pragma unroll
                for (int nf = 0; nf < 5; ++nf)
                    MMAF16(acc16[mf][nf], afr[mf], bfr[nf]);
        }
        // ---- promote fp16 segment -> fp32 every 2 chunks (and at the end) ----
        if ((kc & 1) || kc == NCH - 1) {
            #pragma unroll
            for (int mf = 0; mf < 2; ++mf)
                #pragma unroll
                for (int nf = 0; nf < 5; ++nf) {
                    __half2 h0 = *reinterpret_cast<__half2*>(&acc16[mf][nf][0]);
                    __half2 h1 = *reinterpret_cast<__half2*>(&acc16[mf][nf][1]);
                    float2 f0 = __half22float2(h0);
                    float2 f1 = __half22float2(h1);
                    acc[mf][nf][0] += f0.x; acc[mf][nf][1] += f0.y;
                    acc[mf][nf][2] += f1.x; acc[mf][nf][3] += f1.y;
                    acc16[mf][nf][0] = 0u;  acc16[mf][nf][1] = 0u;
                }
        }
        // ---- refill freed buffer with chunk kc+2 ----
        if (kc < NCH - 1) {
            __syncthreads();
            if (kc < NCH - 2) {
                issue_chunk(sb + bo, kc + 2, m0, n0, tid);
                CP_WAIT(1);
            } else {
                CP_WAIT(0);
            }
            __syncthreads();
        }
    }

    // ---- epilogue: acc -> g_Yt[n][m]  (N exact: no guards) ----
    #pragma unroll
    for (int mf = 0; mf < 2; ++mf) {
        const int mbase = m0 + m_warp + mf * 16 + (lane >> 2);
        #pragma unroll
        for (int nf = 0; nf < 5; ++nf) {
            const int nbase = n0 + n_warp + nf * 8 + 2 * (lane & 3);
            g_Yt[(size_t)nbase * Mv + mbase]           = acc[mf][nf][0];
            g_Yt[(size_t)(nbase + 1) * Mv + mbase]     = acc[mf][nf][1];
            g_Yt[(size_t)nbase * Mv + mbase + 8]       = acc[mf][nf][2];
            g_Yt[(size_t)(nbase + 1) * Mv + mbase + 8] = acc[mf][nf][3];
        }
    }

    // ---- pair handshake: second finisher computes dist for (b = mb>>1, 20 protos) ----
    __shared__ int s_old;
    __threadfence();
    __syncthreads();
    if (tid == 0) s_old = atomicExch(&g_Flag[nb * 64 + (blockIdx.y >> 1)], 1);
    __syncthreads();
    if (s_old != 1) return;
    __threadfence();

    const int b = blockIdx.y >> 1;
    for (int t = wid; t < 20; t += 8) {
        int p = 20 * nb + t;
        int g = (p < 34) ? 0 : (p < 67) ? 1 : 2;
        int d = g + 1;
        int Lout = Lv - 3 * d;                             // 253/250/247
        int pbase = (g == 0) ? 0 : (g == 1) ? 34 : 67;
        int nf = (g == 0) ? 34 : 33;
        size_t dbase = (g == 0) ? OFF_D0 : (g == 1) ? OFF_D1 : OFF_D2;
        float* orow = out + dbase + ((size_t)b * nf + (p - pbase)) * Lout;

        const float* y0 = g_Yt + (size_t)(p * 4) * Mv + b * Lv;
        const float* s0 = g_S + b * Lv;
        const float p2 = g_P2[p];

        float mn = 3.402823466e38f;
        #pragma unroll
        for (int it = 0; it < 7; ++it) {                   // l <= 223 always in-bounds
            int l = lane + it * 32;
            float xp = 0.0f, x2 = 0.0f;
            #pragma unroll
            for (int k = 0; k < 4; ++k) {
                xp += y0[(size_t)k * Mv + l + k * d];
                x2 += s0[l + k * d];
            }
            float val = sqrtf(fabsf(x2 - 2.0f * xp + p2));
            orow[l] = val;
            mn = fminf(mn, val);
        }
        {   // tail: l = lane + 224, guard against Lout
            int l = lane + 224;
            if (l < Lout) {
                float xp = 0.0f, x2 = 0.0f;
                #pragma unroll
                for (int k = 0; k < 4; ++k) {
                    xp += y0[(size_t)k * Mv + l + k * d];
                    x2 += s0[l + k * d];
                }
                float val = sqrtf(fabsf(x2 - 2.0f * xp + p2));
                orow[l] = val;
                mn = fminf(mn, val);
            }
        }
        #pragma unroll
        for (int o = 16; o > 0; o >>= 1) mn = fminf(mn, __shfl_xor_sync(0xffffffffu, mn, o));
        if (lane == 0) {
            out[b * Pv + p] = mn;
            atomicAdd(out + OFF_FC + b * 2 + 0, mn * fcw[p]);
            atomicAdd(out + OFF_FC + b * 2 + 1, mn * fcw[Pv + p]);
        }
    }
}

// ---------------- launch ----------------
extern "C" void kernel_launch(void* const* d_in, const int* in_sizes, int n_in,
                              void* d_out, int out_size) {
    const float* emb   = (const float*)d_in[0];   // [64,256,1600]
    const float* proto = (const float*)d_in[1];   // [100,1600,4]
    const float* fcw   = (const float*)d_in[2];   // [2,100]
    float* out = (float*)d_out;

    static int smem_set = 0;
    if (!smem_set) {
        cudaFuncSetAttribute(gemm_mma_kernel,
                             cudaFuncAttributeMaxDynamicSharedMemorySize, SMEM_DYN);
        smem_set = 1;
    }

    prep_kernel<<<2148, 256>>>(emb, proto, out);
    gemm_mma_kernel<<<dim3(5, 128), 256, SMEM_DYN>>>(out, fcw);
}

// round 16
// speedup vs baseline: 2.2447x; 1.1842x over previous
#include <cuda_runtime.h>
#include <cuda_fp16.h>
#include <math.h>
#include <stdint.h>

// ---------------- problem constants ----------------
#define Bv     64
#define Lv     256
#define Ev     1600
#define Pv     100
#define Nv     400          // P*4 (no padding anywhere)
#define NTILE  80           // per-CTA n tile (5 * 80 = 400 exact)
#define Mv     16384        // B*L
#define Kv     1600
#define NCH    25           // Kv/64

// output layout (floats)
#define OFF_D0   6400
#define OFF_D1   556928
#define OFF_D2   1084928
#define OFF_FC   1606592

// ---------------- device scratch ----------------
static __device__ float g_Yt[(size_t)Nv * Mv];   // Y^T [n][m]
static __device__ float g_S[Mv];                 // row sum of squares
static __device__ float g_P2[Pv];                // proto sum of squares
// fp16 chunked operands: row = 64 k values = 128 B
static __device__ __align__(16) unsigned char g_Xc[(size_t)NCH * Mv * 128];   // [kc][m][128]
static __device__ __align__(16) unsigned char g_Bc[(size_t)NCH * Nv * 128];   // [kc][n][128]

// ---------------- smem layout (per CTA, dynamic) ----------------
#define ROWB      144                    // padded smem row stride
#define ASZ       (128 * ROWB)           // 18432
#define BOFF      ASZ
#define BUFSTRIDE (ASZ + 80 * ROWB)      // 29952
#define SMEM_DYN  (2 * BUFSTRIDE)        // 59904

__device__ __forceinline__ uint32_t s2u(const void* p) {
    uint32_t a;
    asm("{ .reg .u64 t; cvta.to.shared.u64 t, %1; cvt.u32.u64 %0, t; }" : "=r"(a) : "l"(p));
    return a;
}

#define CP_ASYNC16(dst, src) \
    asm volatile("cp.async.cg.shared.global [%0], [%1], 16;" :: "r"(dst), "l"(src) : "memory")
#define CP_COMMIT() asm volatile("cp.async.commit_group;" ::: "memory")
#define CP_WAIT(n)  asm volatile("cp.async.wait_group %0;" :: "n"(n) : "memory")

#define LDM_X4(r0, r1, r2, r3, a) \
    asm volatile("ldmatrix.sync.aligned.m8n8.x4.shared.b16 {%0,%1,%2,%3}, [%4];" \
                 : "=r"(r0), "=r"(r1), "=r"(r2), "=r"(r3) : "r"(a))
#define LDM_X2(r0, r1, a) \
    asm volatile("ldmatrix.sync.aligned.m8n8.x2.shared.b16 {%0,%1}, [%2];" \
                 : "=r"(r0), "=r"(r1) : "r"(a))

// fp16 accumulate, fp16 inputs
#define MMAF16(d, a, b) \
    asm volatile("mma.sync.aligned.m16n8k16.row.col.f16.f16.f16.f16 " \
                 "{%0,%1}, {%2,%3,%4,%5}, {%6,%7}, {%0,%1};" \
                 : "+r"((d)[0]), "+r"((d)[1]) \
                 : "r"((a)[0]), "r"((a)[1]), "r"((a)[2]), "r"((a)[3]), \
                   "r"((b)[0]), "r"((b)[1]))

// ---------------- fused prep: X->fp16 chunked + sumsq, proto->fp16 chunked + P2 -----
__global__ void __launch_bounds__(256)
prep_kernel(const float* __restrict__ X, const float* __restrict__ proto,
            float* __restrict__ out) {
    if (blockIdx.x < 2048) {
        // ---- X path: warp per row ----
        int m    = blockIdx.x * 8 + (threadIdx.x >> 5);
        int lane = threadIdx.x & 31;
        const float4* src = reinterpret_cast<const float4*>(X + (size_t)m * Ev);
        float ssq = 0.0f;
        #pragma unroll
        for (int it = 0; it < 7; ++it) {
            int j = lane + it * 32;
            if (j < 200) {
                float4 a = src[2 * j], b = src[2 * j + 1];
                ssq += a.x * a.x + a.y * a.y + a.z * a.z + a.w * a.w
                     + b.x * b.x + b.y * b.y + b.z * b.z + b.w * b.w;
                __half2 p0 = __floats2half2_rn(a.x, a.y);
                __half2 p1 = __floats2half2_rn(a.z, a.w);
                __half2 p2 = __floats2half2_rn(b.x, b.y);
                __half2 p3 = __floats2half2_rn(b.z, b.w);
                uint4 w;
                w.x = *reinterpret_cast<uint32_t*>(&p0);
                w.y = *reinterpret_cast<uint32_t*>(&p1);
                w.z = *reinterpret_cast<uint32_t*>(&p2);
                w.w = *reinterpret_cast<uint32_t*>(&p3);
                int kc = j >> 3, dk = j & 7;
                *reinterpret_cast<uint4*>(g_Xc + ((size_t)kc * Mv + m) * 128 + dk * 16) = w;
            }
        }
        #pragma unroll
        for (int o = 16; o > 0; o >>= 1) ssq += __shfl_xor_sync(0xffffffffu, ssq, o);
        if (lane == 0) g_S[m] = ssq;
    } else {
        // ---- B path: block per proto ----
        int p = blockIdx.x - 2048;                          // 0..99
        if (p == 0 && threadIdx.x < 2 * Bv) out[OFF_FC + threadIdx.x] = 0.0f;
        __shared__ float red[256];
        float s = 0.0f;
        for (int i = threadIdx.x; i < Ev * 4; i += 256) {
            int e = i >> 2, t = i & 3;
            float v = proto[(size_t)p * (Ev * 4) + i];
            s += v * v;
            int n = 4 * p + t;
            int kc = e >> 6, dk = e & 63;
            *reinterpret_cast<__half*>(
                g_Bc + ((size_t)kc * Nv + n) * 128 + dk * 2) = __float2half_rn(v);
        }
        red[threadIdx.x] = s;
        __syncthreads();
        for (int st = 128; st > 0; st >>= 1) {
            if (threadIdx.x < st) red[threadIdx.x] += red[threadIdx.x + st];
            __syncthreads();
        }
        if (threadIdx.x == 0) g_P2[p] = red[0];
    }
}

// ---------------- HMMA GEMM: Yt[n][m] = sum_k X[m][k]*W[k][n] ----------------
// grid (5, 128): 128x80 per CTA; 8 warps (4M x 2N), warp tile 32x40; chunk K=64.
// Pure fp16 accumulation across all K (range-safe); 3 CTAs/SM.
__device__ __forceinline__ void issue_chunk(uint32_t sbuf, int kc, int m0, int n0, int tid) {
    const char* asrc = (const char*)(g_Xc + ((size_t)kc * Mv + m0) * 128);
    #pragma unroll
    for (int u = 0; u < 4; ++u) {
        int i = tid + u * 256;                        // 1024 = 128 rows * 8 quads
        CP_ASYNC16(sbuf + (i >> 3) * ROWB + (i & 7) * 16, asrc + i * 16);
    }
    const char* bsrc = (const char*)(g_Bc + ((size_t)kc * Nv + n0) * 128);
    #pragma unroll
    for (int u = 0; u < 2; ++u) {                     // 640 = 80 rows * 8 quads
        int i = tid + u * 256;
        CP_ASYNC16(sbuf + BOFF + (i >> 3) * ROWB + (i & 7) * 16, bsrc + i * 16);
    }
    if (tid < 128) {
        int i = tid + 512;
        CP_ASYNC16(sbuf + BOFF + (i >> 3) * ROWB + (i & 7) * 16, bsrc + i * 16);
    }
    CP_COMMIT();
}

__global__ void __launch_bounds__(256, 3)
gemm_mma_kernel() {
    extern __shared__ __align__(128) char smem[];
    const uint32_t sb = s2u(smem);
    const int tid  = threadIdx.x;
    const int wid  = tid >> 5;
    const int lane = tid & 31;
    const int nb = blockIdx.x;              // 0..4
    const int m0 = blockIdx.y * 128;
    const int n0 = nb * NTILE;

    const int m_warp = (wid >> 1) * 32;     // 0,32,64,96
    const int n_warp = (wid & 1) * 40;      // 0,40

    const uint32_t aA = sb + (uint32_t)(m_warp + (lane & 15)) * ROWB + (lane >> 4) * 16;
    const uint32_t aB4 = sb + BOFF +
        (uint32_t)(n_warp + ((lane >> 4) << 3) + (lane & 7)) * ROWB + ((lane >> 3) & 1) * 16;
    const int l15 = lane & 15;
    const uint32_t aB2 = sb + BOFF +
        (uint32_t)(n_warp + 32 + (l15 & 7)) * ROWB + ((l15 >> 3) & 1) * 16;

    uint32_t acc16[2][5][2];
    #pragma unroll
    for (int i = 0; i < 2; ++i)
        #pragma unroll
        for (int j = 0; j < 5; ++j) {
            acc16[i][j][0] = 0u; acc16[i][j][1] = 0u;
        }

    // prologue: chunks 0,1 in flight
    issue_chunk(sb, 0, m0, n0, tid);
    issue_chunk(sb + BUFSTRIDE, 1, m0, n0, tid);
    CP_WAIT(1);
    __syncthreads();

    for (int kc = 0; kc < NCH; ++kc) {
        const uint32_t bo = (kc & 1) ? BUFSTRIDE : 0;
        // ---- compute chunk kc: 4 k16 steps ----
        #pragma unroll
        for (int ks = 0; ks < 4; ++ks) {
            uint32_t afr[2][4];
            #pragma unroll
            for (int mf = 0; mf < 2; ++mf)
                LDM_X4(afr[mf][0], afr[mf][1], afr[mf][2], afr[mf][3],
                       aA + bo + mf * (16 * ROWB) + ks * 32);
            uint32_t bfr[5][2];
            #pragma unroll
            for (int p = 0; p < 2; ++p)
                LDM_X4(bfr[2 * p][0], bfr[2 * p][1], bfr[2 * p + 1][0], bfr[2 * p + 1][1],
                       aB4 + bo + p * (16 * ROWB) + ks * 32);
            LDM_X2(bfr[4][0], bfr[4][1], aB2 + bo + ks * 32);
            #pragma unroll
            for (int mf = 0; mf < 2; ++mf)
                #pragma unroll
                for (int nf = 0; nf < 5; ++nf)
                    MMAF16(acc16[mf][nf], afr[mf], bfr[nf]);
        }
        // ---- refill freed buffer with chunk kc+2 ----
        if (kc < NCH - 1) {
            __syncthreads();
            if (kc < NCH - 2) {
                issue_chunk(sb + bo, kc + 2, m0, n0, tid);
                CP_WAIT(1);
            } else {
                CP_WAIT(0);
            }
            __syncthreads();
        }
    }

    // ---- epilogue: fp16 acc -> fp32 -> g_Yt[n][m]  (N exact: no guards) ----
    #pragma unroll
    for (int mf = 0; mf < 2; ++mf) {
        const int mbase = m0 + m_warp + mf * 16 + (lane >> 2);
        #pragma unroll
        for (int nf = 0; nf < 5; ++nf) {
            const int nbase = n0 + n_warp + nf * 8 + 2 * (lane & 3);
            __half2 h0 = *reinterpret_cast<__half2*>(&acc16[mf][nf][0]);
            __half2 h1 = *reinterpret_cast<__half2*>(&acc16[mf][nf][1]);
            float2 f0 = __half22float2(h0);
            float2 f1 = __half22float2(h1);
            g_Yt[(size_t)nbase * Mv + mbase]           = f0.x;
            g_Yt[(size_t)(nbase + 1) * Mv + mbase]     = f0.y;
            g_Yt[(size_t)nbase * Mv + mbase + 8]       = f1.x;
            g_Yt[(size_t)(nbase + 1) * Mv + mbase + 8] = f1.y;
        }
    }
}

// ---------------- distances + per-(b,p) min + fused fc ----------------
__global__ void __launch_bounds__(256)
dist_kernel(float* __restrict__ out, const float* __restrict__ fcw) {
    int idx  = blockIdx.x * 8 + (threadIdx.x >> 5);   // (b,p), grid 800 -> 6400
    int lane = threadIdx.x & 31;
    int p = idx % Pv;
    int b = idx / Pv;
    int g = (p < 34) ? 0 : (p < 67) ? 1 : 2;
    int d = g + 1;
    int Lout = Lv - 3 * d;                             // 253/250/247
    int pbase = (g == 0) ? 0 : (g == 1) ? 34 : 67;
    int nf = (g == 0) ? 34 : 33;
    size_t dbase = (g == 0) ? OFF_D0 : (g == 1) ? OFF_D1 : OFF_D2;
    float* orow = out + dbase + ((size_t)b * nf + (p - pbase)) * Lout;

    const float* y0 = g_Yt + (size_t)(p * 4) * Mv + b * Lv;
    const float* s0 = g_S + b * Lv;
    const float p2 = g_P2[p];

    float mn = 3.402823466e38f;
    #pragma unroll
    for (int it = 0; it < 7; ++it) {                   // l <= 223 always in-bounds
        int l = lane + it * 32;
        float xp = 0.0f, x2 = 0.0f;
        #pragma unroll
        for (int k = 0; k < 4; ++k) {
            xp += y0[(size_t)k * Mv + l + k * d];
            x2 += s0[l + k * d];
        }
        float val = sqrtf(fabsf(x2 - 2.0f * xp + p2));
        orow[l] = val;
        mn = fminf(mn, val);
    }
    {   // tail: l = lane + 224, guard against Lout
        int l = lane + 224;
        if (l < Lout) {
            float xp = 0.0f, x2 = 0.0f;
            #pragma unroll
            for (int k = 0; k < 4; ++k) {
                xp += y0[(size_t)k * Mv + l + k * d];
                x2 += s0[l + k * d];
            }
            float val = sqrtf(fabsf(x2 - 2.0f * xp + p2));
            orow[l] = val;
            mn = fminf(mn, val);
        }
    }
    #pragma unroll
    for (int o = 16; o > 0; o >>= 1) mn = fminf(mn, __shfl_xor_sync(0xffffffffu, mn, o));
    if (lane == 0) {
        out[b * Pv + p] = mn;
        atomicAdd(out + OFF_FC + b * 2 + 0, mn * fcw[p]);
        atomicAdd(out + OFF_FC + b * 2 + 1, mn * fcw[Pv + p]);
    }
}

// ---------------- launch ----------------
extern "C" void kernel_launch(void* const* d_in, const int* in_sizes, int n_in,
                              void* d_out, int out_size) {
    const float* emb   = (const float*)d_in[0];   // [64,256,1600]
    const float* proto = (const float*)d_in[1];   // [100,1600,4]
    const float* fcw   = (const float*)d_in[2];   // [2,100]
    float* out = (float*)d_out;

    static int smem_set = 0;
    if (!smem_set) {
        cudaFuncSetAttribute(gemm_mma_kernel,
                             cudaFuncAttributeMaxDynamicSharedMemorySize, SMEM_DYN);
        smem_set = 1;
    }

    prep_kernel<<<2148, 256>>>(emb, proto, out);
    gemm_mma_kernel<<<dim3(5, 128), 256, SMEM_DYN>>>();
    dist_kernel<<<800, 256>>>(out, fcw);
}